// round 4
// baseline (speedup 1.0000x reference)
#include <cuda_runtime.h>

#define BN   8
#define NPIX (224*224)   // 50176
#define SS   196
#define EE   768

// ---- scratch (device globals: no allocation allowed) ----
__device__ float g_sumexp[BN*SS];
__device__ float g_pooled[BN*SS*3];
__device__ int   g_count [BN*SS];

__global__ void k_init(){
    int i = blockIdx.x*blockDim.x + threadIdx.x;
    if (i < BN*SS){
        g_sumexp[i] = 0.f;
        g_count[i]  = 0;
        g_pooled[3*i+0] = 0.f;
        g_pooled[3*i+1] = 0.f;
        g_pooled[3*i+2] = 0.f;
    }
}

// Fused pass: per-pixel 196-way argmax label + query score + exp, accumulated
// into per-(b,s) shared-memory slots, flushed once per block with global atomics.
// No max-subtraction needed: softmax is shift-invariant and scores are O(10),
// far from fp32 exp overflow. Non-segment pixels contribute exp(0)=1 each to
// the denominator -> handled in k_out as (NPIX - count).
__global__ void k_main(const float* __restrict__ img,
                       const float* __restrict__ Wseg,
                       const float* __restrict__ bseg,
                       const float* __restrict__ wq){
    __shared__ float4 sW[SS];
    __shared__ float  ssum[SS], sp0[SS], sp1[SS], sp2[SS];
    __shared__ int    scnt[SS];
    int t = threadIdx.x;
    if (t < SS){
        sW[t]  = make_float4(Wseg[3*t], Wseg[3*t+1], Wseg[3*t+2], bseg[t]);
        ssum[t]=0.f; sp0[t]=0.f; sp1[t]=0.f; sp2[t]=0.f; scnt[t]=0;
    }
    __syncthreads();

    int b = blockIdx.y;
    const float* im = img + (size_t)b*3*NPIX;
    float q0 = wq[0], q1 = wq[1], q2 = wq[2];
    int stride = gridDim.x * blockDim.x;

    for (int n = blockIdx.x*blockDim.x + t; n < NPIX; n += stride){
        float c0 = im[n], c1 = im[NPIX+n], c2 = im[2*NPIX+n];
        float best = -3.4e38f; int bi = 0;
        #pragma unroll 7
        for (int s = 0; s < SS; s++){
            float4 w = sW[s];
            float l = fmaf(c0, w.x, fmaf(c1, w.y, fmaf(c2, w.z, w.w)));
            // strict > keeps first-max (lowest index) semantics like jnp.argmax
            bool gt = (l > best);
            best = gt ? l : best;
            bi   = gt ? s : bi;
        }
        float score = fmaf(c0, q0, fmaf(c1, q1, c2*q2));
        float e = expf(score);
        atomicAdd(&ssum[bi], e);
        atomicAdd(&sp0[bi], e*c0);
        atomicAdd(&sp1[bi], e*c1);
        atomicAdd(&sp2[bi], e*c2);
        atomicAdd(&scnt[bi], 1);
    }
    __syncthreads();
    if (t < SS && scnt[t] > 0){
        int gi = b*SS + t;
        atomicAdd(&g_sumexp[gi], ssum[t]);
        atomicAdd(&g_pooled[3*gi+0], sp0[t]);
        atomicAdd(&g_pooled[3*gi+1], sp1[t]);
        atomicAdd(&g_pooled[3*gi+2], sp2[t]);
        atomicAdd(&g_count[gi],  scnt[t]);
    }
}

// Normalize (denominator includes (NPIX-count) exp(0) terms) and project to E.
__global__ void k_out(const float* __restrict__ Wout,
                      const float* __restrict__ bout,
                      float* __restrict__ out){
    int bs = blockIdx.x;            // b*SS + s
    int cnt = g_count[bs];
    float p0 = 0.f, p1 = 0.f, p2 = 0.f;
    if (cnt > 0){
        float D   = g_sumexp[bs] + (float)(NPIX - cnt);
        float inv = 1.0f / D;
        p0 = g_pooled[3*bs+0] * inv;
        p1 = g_pooled[3*bs+1] * inv;
        p2 = g_pooled[3*bs+2] * inv;
    }
    float* o = out + (size_t)bs * EE;
    for (int e = threadIdx.x; e < EE; e += blockDim.x){
        float v = 0.f;
        if (cnt > 0)
            v = fmaf(p0, Wout[3*e+0], fmaf(p1, Wout[3*e+1], fmaf(p2, Wout[3*e+2], bout[e])));
        o[e] = v;
    }
}

extern "C" void kernel_launch(void* const* d_in, const int* in_sizes, int n_in,
                              void* d_out, int out_size) {
    const float* img  = (const float*)d_in[0];   // [8,3,224,224]
    const float* Wseg = (const float*)d_in[1];   // [196,3]
    const float* bseg = (const float*)d_in[2];   // [196]
    const float* wq   = (const float*)d_in[3];   // [3]
    const float* Wout = (const float*)d_in[4];   // [768,3]
    const float* bout = (const float*)d_in[5];   // [768]
    float* out = (float*)d_out;                  // [8,196,768]

    k_init<<<(BN*SS + 255)/256, 256>>>();
    dim3 g(37, BN);                              // 296 blocks ~= 2 per SM
    k_main<<<g, 256>>>(img, Wseg, bseg, wq);
    k_out<<<BN*SS, 256>>>(Wout, bout, out);
}